// round 8
// baseline (speedup 1.0000x reference)
#include <cuda_runtime.h>
#include <cstdint>

#define T_LEN   730
#define B_LEN   1000
#define LENF    15
#define NEARZERO 1e-5f

#define SCAN_BLOCKS 125          // blocks 0..124: scan; block 125: unit hydrograph
#define NBLK        126
#define BLK_T       512
#define UG 10
#define NGROUPS 73               // 73*10 = 730

// smem layout (floats): per (slot, step, basin): 44-float region
//   [0..15]  pair1[m] = (avail, Snew)  at 2m
//   [16..31] pair2[m] = (Gnew, Y)     at 16+2m
// strides chosen for bank-conflict-freedom (44 % 32 = 12; 356 % 32 = 4)
#define BAS_S  44
#define STEP_S 356
#define SLOT_S (STEP_S * UG)     // 3560
#define SRED_FLOATS (2 * SLOT_S)

__device__ float g_qsurf[T_LEN * B_LEN];
__device__ float g_qgw  [T_LEN * B_LEN];
__device__ float g_uh   [B_LEN * LENF];

__device__ unsigned g_count = 0;
__device__ unsigned g_sense = 0;

__device__ __forceinline__ void grid_barrier() {
    __syncthreads();
    if (threadIdx.x == 0) {
        volatile unsigned* vs = &g_sense;
        unsigned s = *vs;
        __threadfence();
        if (atomicAdd(&g_count, 1u) == NBLK - 1u) {
            g_count = 0;
            __threadfence();
            *vs = s ^ 1u;
        } else {
            while (*vs == s) { }
            __threadfence();
        }
    }
    __syncthreads();
}

__device__ __forceinline__ float f_sqrt_approx(float x) {
    float r; asm("sqrt.approx.f32 %0, %1;" : "=f"(r) : "f"(x)); return r;
}
__device__ __forceinline__ float f_ex2(float x) {
    float r; asm("ex2.approx.f32 %0, %1;" : "=f"(r) : "f"(x)); return r;
}

#define BAR_SYNC(id)   asm volatile("bar.sync %0, 128;"   :: "r"(id) : "memory")
#define BAR_ARRIVE(id) asm volatile("bar.arrive %0, 128;" :: "r"(id) : "memory")

// ---------------------------------------------------------------------------
__device__ void uh_for_basin(const float* __restrict__ raw, int b) {
    float ra = raw[b * 34 + 32] * 2.9f;
    float rb = raw[b * 34 + 33] * 6.5f;
    float aa    = fmaxf(ra, 0.0f) + 0.1f;
    float theta = fmaxf(rb, 0.0f) + 0.5f;
    float lg   = lgammaf(aa);
    float lth  = logf(theta);
    float ivth = 1.0f / theta;
    float w[LENF];
    float s = 0.0f;
#pragma unroll
    for (int k = 0; k < LENF; ++k) {
        float t = (float)k + 0.5f;
        float lw = (aa - 1.0f) * logf(t) - t * ivth - lg - aa * lth;
        w[k] = expf(lw);
        s += w[k];
    }
    float inv = 1.0f / s;
#pragma unroll
    for (int k = 0; k < LENF; ++k)
        g_uh[b * LENF + k] = w[k] * inv;
}

// ---------------------------------------------------------------------------
__global__ void __launch_bounds__(BLK_T) fused_kernel(
    const float* __restrict__ x,      // (T,B,2)
    const float* __restrict__ raw,    // (B,34)
    float* __restrict__ out)          // (T,B,6)
{
    __shared__ __align__(16) float sred[SRED_FLOATS];
    const int tid = threadIdx.x;

    if (blockIdx.x == SCAN_BLOCKS) {
        for (int b = tid; b < B_LEN; b += BLK_T) uh_for_basin(raw, b);
    } else if (tid < 64) {
        // ============ producers: minimal recurrence, 2x STS.64 ============
        int bl = tid >> 3;
        int m  = tid & 7;
        int b  = blockIdx.x * 8 + bl;

        float a   = fmaf(raw[b*34 +      m], 0.9f, 0.1f);
        float bb  = fmaf(raw[b*34 +  8 + m], 450.0f, 50.0f);
        float c   = raw[b*34 + 16 + m];
        float d   = fmaf(raw[b*34 + 24 + m], 0.89f, 0.01f);

        float inv2a  = 0.5f / a;
        float binv2a = bb * inv2a;
        float boa    = bb / a;
        float nl2eob = -1.44269504088896f / bb;
        float inv1pd = 1.0f / (1.0f + d);

        float S = 50.0f, G = 10.0f;

        float2* my1 = (float2*)(sred + bl * BAS_S + 2 * m);        // (avail,Snew)
        float2* my2 = (float2*)(sred + bl * BAS_S + 16 + 2 * m);   // (Gnew,Y)

        const float2* __restrict__ xv = (const float2*)x;
        float2 cur[UG], nxt[UG];
#pragma unroll
        for (int i = 0; i < UG; ++i) cur[i] = __ldg(xv + i * B_LEN + b);

        for (int gi = 0; gi < NGROUPS; ++gi) {
            if (gi < NGROUPS - 1) {
                const float2* base = xv + (gi + 1) * UG * B_LEN + b;
#pragma unroll
                for (int i = 0; i < UG; ++i) nxt[i] = __ldg(base + i * B_LEN);
            }
            int slot = gi & 1;
            if (gi >= 2) BAR_SYNC(3 + slot);
            int so = slot * SLOT_S / 2;   // float2 units
#pragma unroll
            for (int i = 0; i < UG; ++i) {
                float p   = cur[i].x;
                float pet = cur[i].y;
                float W    = p + S;
                float term = fmaf(W, inv2a, binv2a);
                float arg  = fmaxf(fmaf(term, term, -(W * boa)), NEARZERO);
                float Y    = term - f_sqrt_approx(arg);
                float Snew = Y * f_ex2(pet * nl2eob);
                float avail = W - Y;
                float Gnew = fmaf(c, avail, G) * inv1pd;
                S = Snew;
                G = Gnew;
                my1[so + i * (STEP_S / 2)] = make_float2(avail, Snew);
                my2[so + i * (STEP_S / 2)] = make_float2(Gnew, Y);
            }
            BAR_ARRIVE(1 + slot);
            if (gi < NGROUPS - 1) {
#pragma unroll
                for (int i = 0; i < UG; ++i) cur[i] = nxt[i];
            }
        }
    } else if (tid < 128) {
        // ============ consumers: all 5 outputs per (basin, step) ============
        int rtid = tid - 64;
        bool active = (rtid < 40);
        int bl = rtid & 7;
        int s0 = rtid >> 3;          // 0..4 for active lanes
        int b  = blockIdx.x * 8 + bl;

        // per-channel weights for this basin
        float wq[8], wd[8];
#pragma unroll
        for (int k = 0; k < 8; ++k) {
            wq[k] = 1.0f - raw[b*34 + 16 + k];                    // (1-c)
            wd[k] = fmaf(raw[b*34 + 24 + k], 0.89f, 0.01f);       // d
        }

        const float* base0 = sred + bl * BAS_S;

        for (int gi = 0; gi < NGROUPS; ++gi) {
            int slot = gi & 1;
            BAR_SYNC(1 + slot);
            if (active) {
                int tbase = gi * UG;
#pragma unroll
                for (int half = 0; half < 2; ++half) {
                    int s = s0 + half * 5;        // step within group
                    int t = tbase + s;
                    const float4* p1 = (const float4*)(base0 + slot * SLOT_S + s * STEP_S);
                    const float4* p2 = (const float4*)(base0 + slot * SLOT_S + s * STEP_S + 16);
                    float4 A0 = p1[0], A1 = p1[1], A2 = p1[2], A3 = p1[3];
                    float4 B0 = p2[0], B1 = p2[1], B2 = p2[2], B3 = p2[3];

                    float sumS = ((A0.y + A0.w) + (A1.y + A1.w))
                               + ((A2.y + A2.w) + (A3.y + A3.w));
                    float sumG = ((B0.x + B0.z) + (B1.x + B1.z))
                               + ((B2.x + B2.z) + (B3.x + B3.z));
                    float sumY = ((B0.y + B0.w) + (B1.y + B1.w))
                               + ((B2.y + B2.w) + (B3.y + B3.w));
                    float dQS = wq[0]*A0.x + wq[1]*A0.z + wq[2]*A1.x + wq[3]*A1.z
                              + wq[4]*A2.x + wq[5]*A2.z + wq[6]*A3.x + wq[7]*A3.z;
                    float dQG = wd[0]*B0.x + wd[1]*B0.z + wd[2]*B1.x + wd[3]*B1.z
                              + wd[4]*B2.x + wd[5]*B2.z + wd[6]*B3.x + wd[7]*B3.z;

                    g_qsurf[t * B_LEN + b] = dQS * 0.125f;
                    g_qgw  [t * B_LEN + b] = dQG * 0.125f;
                    float* o = out + t * (6 * B_LEN) + b * 6;
                    o[3] = (sumY - sumS) * 0.125f;
                    o[4] = sumS * 0.125f;
                    o[5] = sumG * 0.125f;
                }
            }
            BAR_ARRIVE(3 + slot);
        }
    }

    // ===================== barrier =====================
    grid_barrier();

    // ===================== Phase 2: conv (TPER=5) =====================
    const int nItems = (T_LEN / 5) * B_LEN;   // 146000
    for (int item = blockIdx.x * BLK_T + tid; item < nItems; item += NBLK * BLK_T) {
        int b  = item % B_LEN;
        int t0 = (item / B_LEN) * 5;

        float uh[LENF];
#pragma unroll
        for (int k = 0; k < LENF; ++k) uh[k] = __ldg(&g_uh[b * LENF + k]);

        float qs1[LENF - 1 + 5];
        float qs2[LENF - 1 + 5];
#pragma unroll
        for (int i = 0; i < LENF - 1 + 5; ++i) {
            int tt = t0 - (LENF - 1) + i;
            bool ok = (tt >= 0);
            qs1[i] = ok ? __ldg(&g_qsurf[tt * B_LEN + b]) : 0.0f;
            qs2[i] = ok ? __ldg(&g_qgw  [tt * B_LEN + b]) : 0.0f;
        }
#pragma unroll
        for (int j = 0; j < 5; ++j) {
            float a1 = 0.0f, a2 = 0.0f;
#pragma unroll
            for (int k = 0; k < LENF; ++k) {
                a1 = fmaf(uh[k], qs1[LENF - 1 + j - k], a1);
                a2 = fmaf(uh[k], qs2[LENF - 1 + j - k], a2);
            }
            float* o = out + (t0 + j) * (6 * B_LEN) + b * 6;
            o[0] = a1 + a2;   // routed Qsim (conv is linear)
            o[1] = a1;        // routed Qsurf
            o[2] = a2;        // routed Qgw
        }
    }
}

// ---------------------------------------------------------------------------
extern "C" void kernel_launch(void* const* d_in, const int* in_sizes, int n_in,
                              void* d_out, int out_size) {
    const float* x   = (const float*)d_in[0];   // (730,1000,2)
    const float* raw = (const float*)d_in[1];   // (1000,34)
    float* out = (float*)d_out;                 // (730,1000,6)

    fused_kernel<<<NBLK, BLK_T>>>(x, raw, out);
}